// round 10
// baseline (speedup 1.0000x reference)
#include <cuda_runtime.h>
#include <math.h>

#define NMAX 100000
#define EMAX 1600000
#define NEG_SLOPE 0.2f
#define LN_EPS 1e-5f
#define SCAN_CHUNK 512

// ---------------- scratch (device globals; no allocation) ----------------
__device__ __align__(16) float g_h[NMAX * 64];   // per-layer linear output
__device__ __align__(16) float g_x1[NMAX * 64];  // layer-1 output
__device__ __align__(16) float g_s[NMAX * 4];    // layer-1 src logits
__device__ __align__(16) float g_d[NMAX * 4];    // layer-1 dst logits
__device__ __align__(16) float g_s2[NMAX * 4];   // layer-2 src logits
__device__ __align__(16) float g_d2[NMAX * 4];   // layer-2 dst logits
__device__ __align__(16) float g_ws[8 * 72];     // folded attn weights (layer 1)
__device__ __align__(16) float g_ws2[8 * 64];    // folded attn weights (layer 2)
__device__ int   g_deg[NMAX];
__device__ int   g_rowptr[NMAX + 1];
__device__ int   g_wptr[NMAX];
__device__ int   g_csrc[EMAX];
__device__ int   g_part[1024];
__device__ float g_gacc[64];

__device__ __forceinline__ float lrelu(float v) {
    return v > 0.0f ? v : NEG_SLOPE * v;
}

// ---------------- cp.async helpers ----------------
__device__ __forceinline__ unsigned smem_u32(const void* p) {
    return (unsigned)__cvta_generic_to_shared(p);
}
__device__ __forceinline__ void cp16(void* dst, const void* src) {
    asm volatile("cp.async.cg.shared.global [%0], [%1], 16;"
                 :: "r"(smem_u32(dst)), "l"(src));
}
__device__ __forceinline__ void cp_commit() {
    asm volatile("cp.async.commit_group;" ::: "memory");
}
template <int N>
__device__ __forceinline__ void cp_wait() {
    asm volatile("cp.async.wait_group %0;" :: "n"(N) : "memory");
}

// ---------------- small fills ----------------
__global__ void filli(int* p, int v, int n) {
    int i = blockIdx.x * blockDim.x + threadIdx.x;
    if (i < n) p[i] = v;
}

// ---------------- CSR build (scalar — vectorized version regressed) ----------------
__global__ void hist_deg(const int* __restrict__ ei, int E, int* __restrict__ deg) {
    int e = blockIdx.x * blockDim.x + threadIdx.x;
    if (e < E) atomicAdd(&deg[ei[E + e]], 1);
}

__global__ void scanA(const int* __restrict__ deg, int n, int* __restrict__ part) {
    __shared__ int sm[SCAN_CHUNK];
    int gid = blockIdx.x * SCAN_CHUNK + threadIdx.x;
    sm[threadIdx.x] = (gid < n) ? deg[gid] : 0;
    __syncthreads();
    for (int off = SCAN_CHUNK / 2; off > 0; off >>= 1) {
        if (threadIdx.x < off) sm[threadIdx.x] += sm[threadIdx.x + off];
        __syncthreads();
    }
    if (threadIdx.x == 0) part[blockIdx.x] = sm[0];
}

__global__ void scanB(int* __restrict__ part, int nb, int n, int* __restrict__ rowptr) {
    __shared__ int sm[1024];
    int t = threadIdx.x;
    int v = (t < nb) ? part[t] : 0;
    sm[t] = v;
    __syncthreads();
    for (int off = 1; off < 1024; off <<= 1) {
        int add = (t >= off) ? sm[t - off] : 0;
        __syncthreads();
        sm[t] += add;
        __syncthreads();
    }
    if (t < nb) part[t] = sm[t] - v;
    if (t == 1023) rowptr[n] = sm[1023];
}

__global__ void scanC(const int* __restrict__ deg, int n, const int* __restrict__ part,
                      int* __restrict__ rowptr, int* __restrict__ wptr) {
    __shared__ int sm[SCAN_CHUNK];
    int t = threadIdx.x;
    int gid = blockIdx.x * SCAN_CHUNK + t;
    int v = (gid < n) ? deg[gid] : 0;
    sm[t] = v;
    __syncthreads();
    for (int off = 1; off < SCAN_CHUNK; off <<= 1) {
        int add = (t >= off) ? sm[t - off] : 0;
        __syncthreads();
        sm[t] += add;
        __syncthreads();
    }
    if (gid < n) {
        int r = part[blockIdx.x] + sm[t] - v;
        rowptr[gid] = r;
        wptr[gid] = r;
    }
}

__global__ void scatter_csr(const int* __restrict__ ei, int E,
                            int* __restrict__ wptr, int* __restrict__ csrc) {
    int e = blockIdx.x * blockDim.x + threadIdx.x;
    if (e >= E) return;
    int d = ei[E + e];
    int pos = atomicAdd(&wptr[d], 1);
    csrc[pos] = ei[e];
}

// ---------------- fold attention vectors into ws ----------------
template <int IN_DIM>
__global__ void prep_ws(const float* __restrict__ W, const float* __restrict__ a_src,
                        const float* __restrict__ a_dst, float* __restrict__ ws) {
    int idx = blockIdx.x * blockDim.x + threadIdx.x;
    if (idx >= 8 * IN_DIM) return;
    int o = idx / IN_DIM, k = idx % IN_DIM;
    const float* a = (o < 4) ? a_src : a_dst;
    int hd = o & 3;
    float acc = 0.0f;
#pragma unroll
    for (int c = 0; c < 16; c++)
        acc = fmaf(W[k * 64 + hd * 16 + c], a[hd * 16 + c], acc);
    ws[idx] = acc;
}

// ---------------- staging helper (16 nodes per tile) ----------------
template <int TEMP, int IN_DIM>
__device__ __forceinline__ void stage_cp(float* sbuf, const float* __restrict__ in,
                                         const float* __restrict__ tf,
                                         const float* __restrict__ Wt,
                                         const float* __restrict__ bt,
                                         int g0, int n, int tid) {
    if (TEMP) {
        for (int i = tid; i < 16 * 14; i += 256) {
            int nl = i / 14, c4 = i - nl * 14;
            int node = g0 + nl;
            if (node < n)
                cp16(&sbuf[nl * 72 + c4 * 4], &in[(long)node * 56 + c4 * 4]);
        }
        if (tid < 16 * 4) {
            int nl = tid >> 2, q = tid & 3;
            int node = g0 + nl;
            if (node < n) {
                float tv = tf[node];
                float4 r;
                r.x = fmaxf(fmaf(tv, Wt[q * 4 + 0], bt[q * 4 + 0]), 0.0f);
                r.y = fmaxf(fmaf(tv, Wt[q * 4 + 1], bt[q * 4 + 1]), 0.0f);
                r.z = fmaxf(fmaf(tv, Wt[q * 4 + 2], bt[q * 4 + 2]), 0.0f);
                r.w = fmaxf(fmaf(tv, Wt[q * 4 + 3], bt[q * 4 + 3]), 0.0f);
                *(float4*)&sbuf[nl * 72 + 56 + q * 4] = r;
            }
        }
    } else {
        if (tid < 16 * 16) {
            int nl = tid >> 4, c4 = tid & 15;
            int node = g0 + nl;
            if (node < n)
                cp16(&sbuf[nl * 64 + c4 * 4], &in[(long)node * 64 + c4 * 4]);
        }
    }
}

// ---------------- linear layer: k-split across lane pairs ----------------
// 256 threads: half = tid&1, j = (tid>>1)&63, group = tid>>7 (0..1).
// Each group handles 8 nodes (16 nodes/tile). Thread holds HALF its W column
// (wreg[IN_DIM/2]) -> ~75 regs -> 3 blocks/SM. Halves combined via shfl_down(1).
// EPI=1: also computes s/d = x . ws (layer 1). ZG=1: block 0 zeroes gacc.
template <int TEMP, int IN_DIM, int EPI, int ZG>
__global__ void __launch_bounds__(256, 3)
lin_h(const float* __restrict__ in,
      const float* __restrict__ tf, const float* __restrict__ Wt,
      const float* __restrict__ bt,
      const float* __restrict__ W, const float* __restrict__ ws,
      float* __restrict__ h_out,
      float* __restrict__ s_out, float* __restrict__ d_out_,
      float* __restrict__ gacc, int n) {
    const int K2 = IN_DIM / 2;
    __shared__ float sx[2][16 * IN_DIM];
    __shared__ float sws[EPI ? 8 * IN_DIM : 8];
    int tid = threadIdx.x;
    int half = tid & 1;
    int j = (tid >> 1) & 63;
    int group = tid >> 7;          // 0..1

    if (ZG && blockIdx.x == 0 && tid < 64) gacc[tid] = 0.0f;
    if (EPI) {
        for (int i = tid; i < 8 * IN_DIM; i += 256) sws[i] = ws[i];
    }

    float wreg[K2];
#pragma unroll
    for (int k = 0; k < K2; k++) wreg[k] = W[(half * K2 + k) * 64 + j];

    int stride = gridDim.x * 16;
    int g0 = blockIdx.x * 16;
    if (g0 >= n) return;

    stage_cp<TEMP, IN_DIM>(sx[0], in, tf, Wt, bt, g0, n, tid);
    cp_commit();
    int buf = 0;

    for (; g0 < n; g0 += stride) {
        int gn = g0 + stride;
        bool have_next = gn < n;
        if (have_next) {
            stage_cp<TEMP, IN_DIM>(sx[buf ^ 1], in, tf, Wt, bt, gn, n, tid);
            cp_commit();
            cp_wait<1>();
        } else {
            cp_wait<0>();
        }
        __syncthreads();

        float acc[8];
#pragma unroll
        for (int r = 0; r < 8; r++) acc[r] = 0.0f;
        // this thread's half of each x row (16B-aligned: K2*4 = 144 or 128)
        const float* xbase = &sx[buf][(group * 8) * IN_DIM + half * K2];
#pragma unroll
        for (int k = 0; k < K2; k += 4) {
#pragma unroll
            for (int r = 0; r < 8; r++) {
                float4 xv = *(const float4*)&xbase[r * IN_DIM + k];
                acc[r] = fmaf(wreg[k + 0], xv.x, acc[r]);
                acc[r] = fmaf(wreg[k + 1], xv.y, acc[r]);
                acc[r] = fmaf(wreg[k + 2], xv.z, acc[r]);
                acc[r] = fmaf(wreg[k + 3], xv.w, acc[r]);
            }
        }
        // combine k-halves: lanes 2u (half0) <- 2u+1 (half1)
#pragma unroll
        for (int r = 0; r < 8; r++)
            acc[r] += __shfl_down_sync(0xffffffffu, acc[r], 1);
        if (half == 0) {
#pragma unroll
            for (int r = 0; r < 8; r++) {
                int node = g0 + group * 8 + r;
                if (node < n) h_out[(long)node * 64 + j] = acc[r];
            }
        }

        if (EPI) {
            // s/d epilogue: 128 threads = 16 nodes x 8 outputs (full-k dot)
            int nl = tid >> 3, o = tid & 7;
            if (nl < 16) {
                int node = g0 + nl;
                if (node < n) {
                    const float* xr = &sx[buf][nl * IN_DIM];
                    const float* wr = &sws[o * IN_DIM];
                    float a2 = 0.0f;
#pragma unroll
                    for (int k = 0; k < IN_DIM; k += 4) {
                        float4 xv = *(const float4*)&xr[k];
                        float4 wv = *(const float4*)&wr[k];
                        a2 = fmaf(xv.x, wv.x, a2);
                        a2 = fmaf(xv.y, wv.y, a2);
                        a2 = fmaf(xv.z, wv.z, a2);
                        a2 = fmaf(xv.w, wv.w, a2);
                    }
                    if (o < 4) s_out[node * 4 + o] = a2;
                    else       d_out_[node * 4 + o - 4] = a2;
                }
            }
        }
        __syncthreads();
        buf ^= 1;
    }
}

// ---------------- fused GAT aggregation + softmax-norm + LN + ReLU ----------------
// Full warp per dst node, two 16-lane sub-halves, x4 unroll.
// EPI_SD=1: also computes next layer's s2/d2. EPI_POOL=1: mean-pool numerator.
template <int EPI_SD, int EPI_POOL>
__global__ void gat_agg(const int* __restrict__ rowptr, const int* __restrict__ csrc,
                        const float* __restrict__ s_, const float* __restrict__ d_,
                        const float* __restrict__ h_,
                        const float* __restrict__ b,
                        const float* __restrict__ gma, const float* __restrict__ bta,
                        const float* __restrict__ ws2,
                        float* __restrict__ s2_out, float* __restrict__ d2_out,
                        float* __restrict__ gacc,
                        float* __restrict__ out, int n) {
    __shared__ float pool[EPI_POOL ? 8 : 1][EPI_POOL ? 64 : 1];
    int lane = threadIdx.x & 31;
    int sub  = lane >> 4;
    int l    = lane & 15;
    int wid  = threadIdx.x >> 5;
    int node = blockIdx.x * (blockDim.x >> 5) + wid;
    bool valid = node < n;

    if (valid) {
        int head = l >> 2;
        float dlog = d_[node * 4 + head];

        float4 acc = make_float4(0.f, 0.f, 0.f, 0.f);
        float z = 0.0f;
        if (sub == 0) {   // self-loop
            float w = __expf(lrelu(s_[node * 4 + head] + dlog));
            z = w;
            float4 hv = *(const float4*)&h_[(long)node * 64 + l * 4];
            acc = make_float4(w * hv.x, w * hv.y, w * hv.z, w * hv.w);
        }

        int beg = rowptr[node], end = rowptr[node + 1];
        int i = beg + sub;
        for (; i + 6 < end; i += 8) {
            int s0 = csrc[i];
            int s1 = csrc[i + 2];
            int s2 = csrc[i + 4];
            int s3 = csrc[i + 6];
            float e0 = s_[s0 * 4 + head];
            float e1 = s_[s1 * 4 + head];
            float e2 = s_[s2 * 4 + head];
            float e3 = s_[s3 * 4 + head];
            float4 h0 = *(const float4*)&h_[(long)s0 * 64 + l * 4];
            float4 h1 = *(const float4*)&h_[(long)s1 * 64 + l * 4];
            float4 h2 = *(const float4*)&h_[(long)s2 * 64 + l * 4];
            float4 h3 = *(const float4*)&h_[(long)s3 * 64 + l * 4];
            float w0 = __expf(lrelu(e0 + dlog));
            float w1 = __expf(lrelu(e1 + dlog));
            float w2 = __expf(lrelu(e2 + dlog));
            float w3 = __expf(lrelu(e3 + dlog));
            z += (w0 + w1) + (w2 + w3);
            acc.x = fmaf(w0, h0.x, acc.x); acc.x = fmaf(w1, h1.x, acc.x);
            acc.x = fmaf(w2, h2.x, acc.x); acc.x = fmaf(w3, h3.x, acc.x);
            acc.y = fmaf(w0, h0.y, acc.y); acc.y = fmaf(w1, h1.y, acc.y);
            acc.y = fmaf(w2, h2.y, acc.y); acc.y = fmaf(w3, h3.y, acc.y);
            acc.z = fmaf(w0, h0.z, acc.z); acc.z = fmaf(w1, h1.z, acc.z);
            acc.z = fmaf(w2, h2.z, acc.z); acc.z = fmaf(w3, h3.z, acc.z);
            acc.w = fmaf(w0, h0.w, acc.w); acc.w = fmaf(w1, h1.w, acc.w);
            acc.w = fmaf(w2, h2.w, acc.w); acc.w = fmaf(w3, h3.w, acc.w);
        }
        for (; i < end; i += 2) {
            int s0 = csrc[i];
            float w0 = __expf(lrelu(s_[s0 * 4 + head] + dlog));
            float4 h0 = *(const float4*)&h_[(long)s0 * 64 + l * 4];
            z += w0;
            acc.x = fmaf(w0, h0.x, acc.x);
            acc.y = fmaf(w0, h0.y, acc.y);
            acc.z = fmaf(w0, h0.z, acc.z);
            acc.w = fmaf(w0, h0.w, acc.w);
        }

        z     += __shfl_xor_sync(0xffffffffu, z, 16);
        acc.x += __shfl_xor_sync(0xffffffffu, acc.x, 16);
        acc.y += __shfl_xor_sync(0xffffffffu, acc.y, 16);
        acc.z += __shfl_xor_sync(0xffffffffu, acc.z, 16);
        acc.w += __shfl_xor_sync(0xffffffffu, acc.w, 16);

        float zinv = 1.0f / (z + 1e-16f);
        float4 v;
        v.x = acc.x * zinv + b[l * 4 + 0];
        v.y = acc.y * zinv + b[l * 4 + 1];
        v.z = acc.z * zinv + b[l * 4 + 2];
        v.w = acc.w * zinv + b[l * 4 + 3];

        float sum = v.x + v.y + v.z + v.w;
        float sq  = v.x * v.x + v.y * v.y + v.z * v.z + v.w * v.w;
#pragma unroll
        for (int off = 8; off; off >>= 1) {
            sum += __shfl_xor_sync(0xffffffffu, sum, off, 16);
            sq  += __shfl_xor_sync(0xffffffffu, sq, off, 16);
        }
        float mean = sum * (1.0f / 64.0f);
        float var  = sq * (1.0f / 64.0f) - mean * mean;
        float inv  = rsqrtf(var + LN_EPS);
        float4 o;
        o.x = (v.x - mean) * inv * gma[l * 4 + 0] + bta[l * 4 + 0];
        o.y = (v.y - mean) * inv * gma[l * 4 + 1] + bta[l * 4 + 1];
        o.z = (v.z - mean) * inv * gma[l * 4 + 2] + bta[l * 4 + 2];
        o.w = (v.w - mean) * inv * gma[l * 4 + 3] + bta[l * 4 + 3];
        o.x = o.x > 0.0f ? o.x : 0.0f;
        o.y = o.y > 0.0f ? o.y : 0.0f;
        o.z = o.z > 0.0f ? o.z : 0.0f;
        o.w = o.w > 0.0f ? o.w : 0.0f;
        if (sub == 0) {
            *(float4*)&out[(long)node * 64 + l * 4] = o;
            if (EPI_POOL)
                *(float4*)&pool[wid][l * 4] = o;
        }

        if (EPI_SD) {
            float p[8];
#pragma unroll
            for (int q = 0; q < 8; q++) {
                float4 wv = *(const float4*)&ws2[q * 64 + l * 4];
                p[q] = fmaf(o.x, wv.x, 0.0f);
                p[q] = fmaf(o.y, wv.y, p[q]);
                p[q] = fmaf(o.z, wv.z, p[q]);
                p[q] = fmaf(o.w, wv.w, p[q]);
            }
#pragma unroll
            for (int q = 0; q < 8; q++) {
#pragma unroll
                for (int off = 8; off; off >>= 1)
                    p[q] += __shfl_xor_sync(0xffffffffu, p[q], off, 16);
            }
            if (sub == 0 && l == 0) {
                *(float4*)&s2_out[node * 4] = make_float4(p[0], p[1], p[2], p[3]);
                *(float4*)&d2_out[node * 4] = make_float4(p[4], p[5], p[6], p[7]);
            }
        }
    } else if (EPI_POOL && sub == 0) {
        *(float4*)&pool[wid][l * 4] = make_float4(0.f, 0.f, 0.f, 0.f);
    }

    if (EPI_POOL) {
        __syncthreads();
        int t = threadIdx.x;
        if (t < 64) {
            float s = 0.0f;
#pragma unroll
            for (int r = 0; r < 8; r++) s += pool[r][t];
            atomicAdd(&gacc[t], s);
        }
    }
}

// ---------------- final MLP on mean-pooled embedding ----------------
__global__ void final_mlp(const float* __restrict__ acc, int n,
                          const float* __restrict__ Wp1, const float* __restrict__ bp1,
                          const float* __restrict__ Wp2, const float* __restrict__ bp2,
                          float* __restrict__ out) {
    __shared__ float gein[64], hid[64];
    int t = threadIdx.x;
    gein[t] = acc[t] / (float)n;
    __syncthreads();
    float a = bp1[t];
#pragma unroll
    for (int k = 0; k < 64; k++) a = fmaf(gein[k], Wp1[k * 64 + t], a);
    hid[t] = a > 0.0f ? a : 0.0f;
    __syncthreads();
    float o = bp2[t];
#pragma unroll
    for (int k = 0; k < 64; k++) o = fmaf(hid[k], Wp2[k * 64 + t], o);
    out[t] = o;
}

// ---------------- host launch ----------------
extern "C" void kernel_launch(void* const* d_in, const int* in_sizes, int n_in,
                              void* d_out, int out_size) {
    const float* x   = (const float*)d_in[0];
    const float* tf  = (const float*)d_in[1];
    const int*   ei  = (const int*)d_in[2];
    const float* Wt  = (const float*)d_in[3];
    const float* bt  = (const float*)d_in[4];
    const float* W1  = (const float*)d_in[5];
    const float* as1 = (const float*)d_in[6];
    const float* ad1 = (const float*)d_in[7];
    const float* b1  = (const float*)d_in[8];
    const float* g1  = (const float*)d_in[9];
    const float* be1 = (const float*)d_in[10];
    const float* W2  = (const float*)d_in[11];
    const float* as2 = (const float*)d_in[12];
    const float* ad2 = (const float*)d_in[13];
    const float* b2  = (const float*)d_in[14];
    const float* g2  = (const float*)d_in[15];
    const float* be2 = (const float*)d_in[16];
    const float* Wp1 = (const float*)d_in[17];
    const float* bp1 = (const float*)d_in[18];
    const float* Wp2 = (const float*)d_in[19];
    const float* bp2 = (const float*)d_in[20];

    int n = in_sizes[0] / 56;
    int E = in_sizes[2] / 2;

    float* out = (float*)d_out;
    float* x2  = out;
    float* ge  = out + (long)n * 64;

    float *h, *x1, *s, *d, *s2, *d2, *gacc, *ws, *ws2;
    int *deg, *rowptr, *wptr, *csrc, *part;
    cudaGetSymbolAddress((void**)&h,      g_h);
    cudaGetSymbolAddress((void**)&x1,     g_x1);
    cudaGetSymbolAddress((void**)&s,      g_s);
    cudaGetSymbolAddress((void**)&d,      g_d);
    cudaGetSymbolAddress((void**)&s2,     g_s2);
    cudaGetSymbolAddress((void**)&d2,     g_d2);
    cudaGetSymbolAddress((void**)&gacc,   g_gacc);
    cudaGetSymbolAddress((void**)&ws,     g_ws);
    cudaGetSymbolAddress((void**)&ws2,    g_ws2);
    cudaGetSymbolAddress((void**)&deg,    g_deg);
    cudaGetSymbolAddress((void**)&rowptr, g_rowptr);
    cudaGetSymbolAddress((void**)&wptr,   g_wptr);
    cudaGetSymbolAddress((void**)&csrc,   g_csrc);
    cudaGetSymbolAddress((void**)&part,   g_part);

    const int TB = 256;
    int ebk = (E + TB - 1) / TB;
    int nwb = (n + 7) / 8;
    int nsb = (n + SCAN_CHUNK - 1) / SCAN_CHUNK;
    const int LGB = 444;           // 3 blocks/SM, 16 nodes per tile

    // 1-3
    prep_ws<72><<<3, TB>>>(W1, as1, ad1, ws);
    filli<<<(n + TB - 1) / TB, TB>>>(deg, 0, n);
    hist_deg<<<ebk, TB>>>(ei, E, deg);
    // 4 (profiled): layer-1 linear + fused s/d
    lin_h<1, 72, 1, 0><<<LGB, TB>>>(x, tf, Wt, bt, W1, ws, h, s, d, gacc, n);
    // 5-8: finish CSR
    scanA<<<nsb, SCAN_CHUNK>>>(deg, n, part);
    scanB<<<1, 1024>>>(part, nsb, n, rowptr);
    scanC<<<nsb, SCAN_CHUNK>>>(deg, n, part, rowptr, wptr);
    scatter_csr<<<ebk, TB>>>(ei, E, wptr, csrc);
    // 9: fold layer-2 attention weights
    prep_ws<64><<<2, TB>>>(W2, as2, ad2, ws2);
    // 10: layer-1 aggregation + fused layer-2 logits
    gat_agg<1, 0><<<nwb, TB>>>(rowptr, csrc, s, d, h, b1, g1, be1, ws2, s2, d2,
                               gacc, x1, n);
    // 11: layer-2 linear (zeroes gacc for the pool epilogue)
    lin_h<0, 64, 0, 1><<<LGB, TB>>>(x1, tf, Wt, bt, W2, ws2, h, s2, d2, gacc, n);
    // 12: layer-2 aggregation + fused global-mean-pool numerator
    gat_agg<0, 1><<<nwb, TB>>>(rowptr, csrc, s2, d2, h, b2, g2, be2, ws2, s2, d2,
                               gacc, x2, n);
    // 13: MLP head
    final_mlp<<<1, 64>>>(gacc, n, Wp1, bp1, Wp2, bp2, ge);
}

// round 11
// speedup vs baseline: 1.1144x; 1.1144x over previous
#include <cuda_runtime.h>
#include <math.h>

#define NMAX 100000
#define EMAX 1600000
#define NEG_SLOPE 0.2f
#define LN_EPS 1e-5f
#define SCAN_CHUNK 512

// ---------------- scratch (device globals; no allocation) ----------------
__device__ __align__(16) float g_h[NMAX * 64];   // per-layer linear output
__device__ __align__(16) float g_x1[NMAX * 64];  // layer-1 output
__device__ __align__(16) float g_s[NMAX * 4];    // layer-1 src logits
__device__ __align__(16) float g_d[NMAX * 4];    // layer-1 dst logits
__device__ __align__(16) float g_s2[NMAX * 4];   // layer-2 src logits
__device__ __align__(16) float g_d2[NMAX * 4];   // layer-2 dst logits
__device__ __align__(16) float g_ws[8 * 72];     // folded attn weights (layer 1)
__device__ __align__(16) float g_ws2[8 * 64];    // folded attn weights (layer 2)
__device__ int   g_deg[NMAX];
__device__ int   g_rowptr[NMAX + 1];
__device__ int   g_wptr[NMAX];
__device__ int   g_csrc[EMAX];
__device__ int   g_part[1024];
__device__ float g_gacc[64];

__device__ __forceinline__ float lrelu(float v) {
    return v > 0.0f ? v : NEG_SLOPE * v;
}

// ---------------- cp.async helpers ----------------
__device__ __forceinline__ unsigned smem_u32(const void* p) {
    return (unsigned)__cvta_generic_to_shared(p);
}
__device__ __forceinline__ void cp16(void* dst, const void* src) {
    asm volatile("cp.async.cg.shared.global [%0], [%1], 16;"
                 :: "r"(smem_u32(dst)), "l"(src));
}
__device__ __forceinline__ void cp_commit() {
    asm volatile("cp.async.commit_group;" ::: "memory");
}
template <int N>
__device__ __forceinline__ void cp_wait() {
    asm volatile("cp.async.wait_group %0;" :: "n"(N) : "memory");
}

// ---------------- small fills ----------------
__global__ void filli(int* p, int v, int n) {
    int i = blockIdx.x * blockDim.x + threadIdx.x;
    if (i < n) p[i] = v;
}

// ---------------- CSR build (scalar; R8 configuration) ----------------
__global__ void hist_deg(const int* __restrict__ ei, int E, int* __restrict__ deg) {
    int e = blockIdx.x * blockDim.x + threadIdx.x;
    if (e < E) atomicAdd(&deg[ei[E + e]], 1);
}

__global__ void scanA(const int* __restrict__ deg, int n, int* __restrict__ part) {
    __shared__ int sm[SCAN_CHUNK];
    int gid = blockIdx.x * SCAN_CHUNK + threadIdx.x;
    sm[threadIdx.x] = (gid < n) ? deg[gid] : 0;
    __syncthreads();
    for (int off = SCAN_CHUNK / 2; off > 0; off >>= 1) {
        if (threadIdx.x < off) sm[threadIdx.x] += sm[threadIdx.x + off];
        __syncthreads();
    }
    if (threadIdx.x == 0) part[blockIdx.x] = sm[0];
}

__global__ void scanB(int* __restrict__ part, int nb, int n, int* __restrict__ rowptr) {
    __shared__ int sm[1024];
    int t = threadIdx.x;
    int v = (t < nb) ? part[t] : 0;
    sm[t] = v;
    __syncthreads();
    for (int off = 1; off < 1024; off <<= 1) {
        int add = (t >= off) ? sm[t - off] : 0;
        __syncthreads();
        sm[t] += add;
        __syncthreads();
    }
    if (t < nb) part[t] = sm[t] - v;
    if (t == 1023) rowptr[n] = sm[1023];
}

__global__ void scanC(const int* __restrict__ deg, int n, const int* __restrict__ part,
                      int* __restrict__ rowptr, int* __restrict__ wptr) {
    __shared__ int sm[SCAN_CHUNK];
    int t = threadIdx.x;
    int gid = blockIdx.x * SCAN_CHUNK + t;
    int v = (gid < n) ? deg[gid] : 0;
    sm[t] = v;
    __syncthreads();
    for (int off = 1; off < SCAN_CHUNK; off <<= 1) {
        int add = (t >= off) ? sm[t - off] : 0;
        __syncthreads();
        sm[t] += add;
        __syncthreads();
    }
    if (gid < n) {
        int r = part[blockIdx.x] + sm[t] - v;
        rowptr[gid] = r;
        wptr[gid] = r;
    }
}

__global__ void scatter_csr(const int* __restrict__ ei, int E,
                            int* __restrict__ wptr, int* __restrict__ csrc) {
    int e = blockIdx.x * blockDim.x + threadIdx.x;
    if (e >= E) return;
    int d = ei[E + e];
    int pos = atomicAdd(&wptr[d], 1);
    csrc[pos] = ei[e];
}

// ---------------- fold attention vectors into ws ----------------
template <int IN_DIM>
__global__ void prep_ws(const float* __restrict__ W, const float* __restrict__ a_src,
                        const float* __restrict__ a_dst, float* __restrict__ ws) {
    int idx = blockIdx.x * blockDim.x + threadIdx.x;
    if (idx >= 8 * IN_DIM) return;
    int o = idx / IN_DIM, k = idx % IN_DIM;
    const float* a = (o < 4) ? a_src : a_dst;
    int hd = o & 3;
    float acc = 0.0f;
#pragma unroll
    for (int c = 0; c < 16; c++)
        acc = fmaf(W[k * 64 + hd * 16 + c], a[hd * 16 + c], acc);
    ws[idx] = acc;
}

// ---------------- staging helper (32 nodes per tile; R8 version) ----------------
template <int TEMP, int IN_DIM>
__device__ __forceinline__ void stage_cp(float* sbuf, const float* __restrict__ in,
                                         const float* __restrict__ tf,
                                         const float* __restrict__ Wt,
                                         const float* __restrict__ bt,
                                         int g0, int n, int tid) {
    if (TEMP) {
        for (int i = tid; i < 32 * 14; i += 256) {
            int nl = i / 14, c4 = i - nl * 14;
            int node = g0 + nl;
            if (node < n)
                cp16(&sbuf[nl * 72 + c4 * 4], &in[(long)node * 56 + c4 * 4]);
        }
        for (int i = tid; i < 32 * 4; i += 256) {
            int nl = i >> 2, q = i & 3;
            int node = g0 + nl;
            if (node < n) {
                float tv = tf[node];
                float4 r;
                r.x = fmaxf(fmaf(tv, Wt[q * 4 + 0], bt[q * 4 + 0]), 0.0f);
                r.y = fmaxf(fmaf(tv, Wt[q * 4 + 1], bt[q * 4 + 1]), 0.0f);
                r.z = fmaxf(fmaf(tv, Wt[q * 4 + 2], bt[q * 4 + 2]), 0.0f);
                r.w = fmaxf(fmaf(tv, Wt[q * 4 + 3], bt[q * 4 + 3]), 0.0f);
                *(float4*)&sbuf[nl * 72 + 56 + q * 4] = r;
            }
        }
    } else {
        for (int i = tid; i < 32 * 16; i += 256) {
            int nl = i >> 4, c4 = i & 15;
            int node = g0 + nl;
            if (node < n)
                cp16(&sbuf[nl * 64 + c4 * 4], &in[(long)node * 64 + c4 * 4]);
        }
    }
}

// ---------------- linear layer: 2 cols/thread + k-split pairs ----------------
// 256 threads: half = tid&1 (k half), jj = (tid>>1)&31 (cols jj, jj+32),
// group = tid>>6 (0..3, 8 nodes each; 32 nodes/tile).
// Each x float4 LDS feeds 8 FMAs (2 cols) -> LDS instruction count halved vs R8.
// wreg = 2 cols x IN_DIM/2 = 72/64 regs. Halves combined with shfl_down(1).
// EPI=1: also computes s/d = x . ws (layer 1). ZG=1: block 0 zeroes gacc.
template <int TEMP, int IN_DIM, int EPI, int ZG>
__global__ void __launch_bounds__(256, 2)
lin_h(const float* __restrict__ in,
      const float* __restrict__ tf, const float* __restrict__ Wt,
      const float* __restrict__ bt,
      const float* __restrict__ W, const float* __restrict__ ws,
      float* __restrict__ h_out,
      float* __restrict__ s_out, float* __restrict__ d_out_,
      float* __restrict__ gacc, int n) {
    const int K2 = IN_DIM / 2;
    __shared__ float sx[2][32 * IN_DIM];
    __shared__ float sws[EPI ? 8 * IN_DIM : 8];
    int tid = threadIdx.x;
    int half = tid & 1;
    int jj = (tid >> 1) & 31;      // columns jj and jj+32
    int group = tid >> 6;          // 0..3

    if (ZG && blockIdx.x == 0 && tid < 64) gacc[tid] = 0.0f;
    if (EPI) {
        for (int i = tid; i < 8 * IN_DIM; i += 256) sws[i] = ws[i];
    }

    float wreg[2][K2];
#pragma unroll
    for (int k = 0; k < K2; k++) {
        wreg[0][k] = W[(half * K2 + k) * 64 + jj];
        wreg[1][k] = W[(half * K2 + k) * 64 + jj + 32];
    }

    int stride = gridDim.x * 32;
    int g0 = blockIdx.x * 32;
    if (g0 >= n) return;

    stage_cp<TEMP, IN_DIM>(sx[0], in, tf, Wt, bt, g0, n, tid);
    cp_commit();
    int buf = 0;

    for (; g0 < n; g0 += stride) {
        int gn = g0 + stride;
        bool have_next = gn < n;
        if (have_next) {
            stage_cp<TEMP, IN_DIM>(sx[buf ^ 1], in, tf, Wt, bt, gn, n, tid);
            cp_commit();
            cp_wait<1>();
        } else {
            cp_wait<0>();
        }
        __syncthreads();

        float acc0[8], acc1[8];
#pragma unroll
        for (int r = 0; r < 8; r++) { acc0[r] = 0.0f; acc1[r] = 0.0f; }
        const float* xbase = &sx[buf][(group * 8) * IN_DIM + half * K2];
#pragma unroll
        for (int k = 0; k < K2; k += 4) {
#pragma unroll
            for (int r = 0; r < 8; r++) {
                float4 xv = *(const float4*)&xbase[r * IN_DIM + k];
                acc0[r] = fmaf(wreg[0][k + 0], xv.x, acc0[r]);
                acc0[r] = fmaf(wreg[0][k + 1], xv.y, acc0[r]);
                acc0[r] = fmaf(wreg[0][k + 2], xv.z, acc0[r]);
                acc0[r] = fmaf(wreg[0][k + 3], xv.w, acc0[r]);
                acc1[r] = fmaf(wreg[1][k + 0], xv.x, acc1[r]);
                acc1[r] = fmaf(wreg[1][k + 1], xv.y, acc1[r]);
                acc1[r] = fmaf(wreg[1][k + 2], xv.z, acc1[r]);
                acc1[r] = fmaf(wreg[1][k + 3], xv.w, acc1[r]);
            }
        }
        // combine k-halves: even lane (half0) <- odd lane (half1)
#pragma unroll
        for (int r = 0; r < 8; r++) {
            acc0[r] += __shfl_down_sync(0xffffffffu, acc0[r], 1);
            acc1[r] += __shfl_down_sync(0xffffffffu, acc1[r], 1);
        }
        if (half == 0) {
#pragma unroll
            for (int r = 0; r < 8; r++) {
                int node = g0 + group * 8 + r;
                if (node < n) {
                    h_out[(long)node * 64 + jj]      = acc0[r];
                    h_out[(long)node * 64 + jj + 32] = acc1[r];
                }
            }
        }

        if (EPI) {
            // s/d epilogue: 256 threads = 32 nodes x 8 outputs (full-k dot)
            int nl = tid >> 3, o = tid & 7;
            int node = g0 + nl;
            if (node < n) {
                const float* xr = &sx[buf][nl * IN_DIM];
                const float* wr = &sws[o * IN_DIM];
                float a2 = 0.0f;
#pragma unroll
                for (int k = 0; k < IN_DIM; k += 4) {
                    float4 xv = *(const float4*)&xr[k];
                    float4 wv = *(const float4*)&wr[k];
                    a2 = fmaf(xv.x, wv.x, a2);
                    a2 = fmaf(xv.y, wv.y, a2);
                    a2 = fmaf(xv.z, wv.z, a2);
                    a2 = fmaf(xv.w, wv.w, a2);
                }
                if (o < 4) s_out[node * 4 + o] = a2;
                else       d_out_[node * 4 + o - 4] = a2;
            }
        }
        __syncthreads();
        buf ^= 1;
    }
}

// ---------------- fused GAT aggregation + softmax-norm + LN + ReLU ----------------
// Full warp per dst node, two 16-lane sub-halves, x4 unroll.
// EPI_SD=1: also computes next layer's s2/d2. EPI_POOL=1: mean-pool numerator.
template <int EPI_SD, int EPI_POOL>
__global__ void gat_agg(const int* __restrict__ rowptr, const int* __restrict__ csrc,
                        const float* __restrict__ s_, const float* __restrict__ d_,
                        const float* __restrict__ h_,
                        const float* __restrict__ b,
                        const float* __restrict__ gma, const float* __restrict__ bta,
                        const float* __restrict__ ws2,
                        float* __restrict__ s2_out, float* __restrict__ d2_out,
                        float* __restrict__ gacc,
                        float* __restrict__ out, int n) {
    __shared__ float pool[EPI_POOL ? 8 : 1][EPI_POOL ? 64 : 1];
    int lane = threadIdx.x & 31;
    int sub  = lane >> 4;
    int l    = lane & 15;
    int wid  = threadIdx.x >> 5;
    int node = blockIdx.x * (blockDim.x >> 5) + wid;
    bool valid = node < n;

    if (valid) {
        int head = l >> 2;
        float dlog = d_[node * 4 + head];

        float4 acc = make_float4(0.f, 0.f, 0.f, 0.f);
        float z = 0.0f;
        if (sub == 0) {   // self-loop
            float w = __expf(lrelu(s_[node * 4 + head] + dlog));
            z = w;
            float4 hv = *(const float4*)&h_[(long)node * 64 + l * 4];
            acc = make_float4(w * hv.x, w * hv.y, w * hv.z, w * hv.w);
        }

        int beg = rowptr[node], end = rowptr[node + 1];
        int i = beg + sub;
        for (; i + 6 < end; i += 8) {
            int s0 = csrc[i];
            int s1 = csrc[i + 2];
            int s2 = csrc[i + 4];
            int s3 = csrc[i + 6];
            float e0 = s_[s0 * 4 + head];
            float e1 = s_[s1 * 4 + head];
            float e2 = s_[s2 * 4 + head];
            float e3 = s_[s3 * 4 + head];
            float4 h0 = *(const float4*)&h_[(long)s0 * 64 + l * 4];
            float4 h1 = *(const float4*)&h_[(long)s1 * 64 + l * 4];
            float4 h2 = *(const float4*)&h_[(long)s2 * 64 + l * 4];
            float4 h3 = *(const float4*)&h_[(long)s3 * 64 + l * 4];
            float w0 = __expf(lrelu(e0 + dlog));
            float w1 = __expf(lrelu(e1 + dlog));
            float w2 = __expf(lrelu(e2 + dlog));
            float w3 = __expf(lrelu(e3 + dlog));
            z += (w0 + w1) + (w2 + w3);
            acc.x = fmaf(w0, h0.x, acc.x); acc.x = fmaf(w1, h1.x, acc.x);
            acc.x = fmaf(w2, h2.x, acc.x); acc.x = fmaf(w3, h3.x, acc.x);
            acc.y = fmaf(w0, h0.y, acc.y); acc.y = fmaf(w1, h1.y, acc.y);
            acc.y = fmaf(w2, h2.y, acc.y); acc.y = fmaf(w3, h3.y, acc.y);
            acc.z = fmaf(w0, h0.z, acc.z); acc.z = fmaf(w1, h1.z, acc.z);
            acc.z = fmaf(w2, h2.z, acc.z); acc.z = fmaf(w3, h3.z, acc.z);
            acc.w = fmaf(w0, h0.w, acc.w); acc.w = fmaf(w1, h1.w, acc.w);
            acc.w = fmaf(w2, h2.w, acc.w); acc.w = fmaf(w3, h3.w, acc.w);
        }
        for (; i < end; i += 2) {
            int s0 = csrc[i];
            float w0 = __expf(lrelu(s_[s0 * 4 + head] + dlog));
            float4 h0 = *(const float4*)&h_[(long)s0 * 64 + l * 4];
            z += w0;
            acc.x = fmaf(w0, h0.x, acc.x);
            acc.y = fmaf(w0, h0.y, acc.y);
            acc.z = fmaf(w0, h0.z, acc.z);
            acc.w = fmaf(w0, h0.w, acc.w);
        }

        z     += __shfl_xor_sync(0xffffffffu, z, 16);
        acc.x += __shfl_xor_sync(0xffffffffu, acc.x, 16);
        acc.y += __shfl_xor_sync(0xffffffffu, acc.y, 16);
        acc.z += __shfl_xor_sync(0xffffffffu, acc.z, 16);
        acc.w += __shfl_xor_sync(0xffffffffu, acc.w, 16);

        float zinv = 1.0f / (z + 1e-16f);
        float4 v;
        v.x = acc.x * zinv + b[l * 4 + 0];
        v.y = acc.y * zinv + b[l * 4 + 1];
        v.z = acc.z * zinv + b[l * 4 + 2];
        v.w = acc.w * zinv + b[l * 4 + 3];

        float sum = v.x + v.y + v.z + v.w;
        float sq  = v.x * v.x + v.y * v.y + v.z * v.z + v.w * v.w;
#pragma unroll
        for (int off = 8; off; off >>= 1) {
            sum += __shfl_xor_sync(0xffffffffu, sum, off, 16);
            sq  += __shfl_xor_sync(0xffffffffu, sq, off, 16);
        }
        float mean = sum * (1.0f / 64.0f);
        float var  = sq * (1.0f / 64.0f) - mean * mean;
        float inv  = rsqrtf(var + LN_EPS);
        float4 o;
        o.x = (v.x - mean) * inv * gma[l * 4 + 0] + bta[l * 4 + 0];
        o.y = (v.y - mean) * inv * gma[l * 4 + 1] + bta[l * 4 + 1];
        o.z = (v.z - mean) * inv * gma[l * 4 + 2] + bta[l * 4 + 2];
        o.w = (v.w - mean) * inv * gma[l * 4 + 3] + bta[l * 4 + 3];
        o.x = o.x > 0.0f ? o.x : 0.0f;
        o.y = o.y > 0.0f ? o.y : 0.0f;
        o.z = o.z > 0.0f ? o.z : 0.0f;
        o.w = o.w > 0.0f ? o.w : 0.0f;
        if (sub == 0) {
            *(float4*)&out[(long)node * 64 + l * 4] = o;
            if (EPI_POOL)
                *(float4*)&pool[wid][l * 4] = o;
        }

        if (EPI_SD) {
            float p[8];
#pragma unroll
            for (int q = 0; q < 8; q++) {
                float4 wv = *(const float4*)&ws2[q * 64 + l * 4];
                p[q] = fmaf(o.x, wv.x, 0.0f);
                p[q] = fmaf(o.y, wv.y, p[q]);
                p[q] = fmaf(o.z, wv.z, p[q]);
                p[q] = fmaf(o.w, wv.w, p[q]);
            }
#pragma unroll
            for (int q = 0; q < 8; q++) {
#pragma unroll
                for (int off = 8; off; off >>= 1)
                    p[q] += __shfl_xor_sync(0xffffffffu, p[q], off, 16);
            }
            if (sub == 0 && l == 0) {
                *(float4*)&s2_out[node * 4] = make_float4(p[0], p[1], p[2], p[3]);
                *(float4*)&d2_out[node * 4] = make_float4(p[4], p[5], p[6], p[7]);
            }
        }
    } else if (EPI_POOL && sub == 0) {
        *(float4*)&pool[wid][l * 4] = make_float4(0.f, 0.f, 0.f, 0.f);
    }

    if (EPI_POOL) {
        __syncthreads();
        int t = threadIdx.x;
        if (t < 64) {
            float s = 0.0f;
#pragma unroll
            for (int r = 0; r < 8; r++) s += pool[r][t];
            atomicAdd(&gacc[t], s);
        }
    }
}

// ---------------- final MLP on mean-pooled embedding ----------------
__global__ void final_mlp(const float* __restrict__ acc, int n,
                          const float* __restrict__ Wp1, const float* __restrict__ bp1,
                          const float* __restrict__ Wp2, const float* __restrict__ bp2,
                          float* __restrict__ out) {
    __shared__ float gein[64], hid[64];
    int t = threadIdx.x;
    gein[t] = acc[t] / (float)n;
    __syncthreads();
    float a = bp1[t];
#pragma unroll
    for (int k = 0; k < 64; k++) a = fmaf(gein[k], Wp1[k * 64 + t], a);
    hid[t] = a > 0.0f ? a : 0.0f;
    __syncthreads();
    float o = bp2[t];
#pragma unroll
    for (int k = 0; k < 64; k++) o = fmaf(hid[k], Wp2[k * 64 + t], o);
    out[t] = o;
}

// ---------------- host launch ----------------
extern "C" void kernel_launch(void* const* d_in, const int* in_sizes, int n_in,
                              void* d_out, int out_size) {
    const float* x   = (const float*)d_in[0];
    const float* tf  = (const float*)d_in[1];
    const int*   ei  = (const int*)d_in[2];
    const float* Wt  = (const float*)d_in[3];
    const float* bt  = (const float*)d_in[4];
    const float* W1  = (const float*)d_in[5];
    const float* as1 = (const float*)d_in[6];
    const float* ad1 = (const float*)d_in[7];
    const float* b1  = (const float*)d_in[8];
    const float* g1  = (const float*)d_in[9];
    const float* be1 = (const float*)d_in[10];
    const float* W2  = (const float*)d_in[11];
    const float* as2 = (const float*)d_in[12];
    const float* ad2 = (const float*)d_in[13];
    const float* b2  = (const float*)d_in[14];
    const float* g2  = (const float*)d_in[15];
    const float* be2 = (const float*)d_in[16];
    const float* Wp1 = (const float*)d_in[17];
    const float* bp1 = (const float*)d_in[18];
    const float* Wp2 = (const float*)d_in[19];
    const float* bp2 = (const float*)d_in[20];

    int n = in_sizes[0] / 56;
    int E = in_sizes[2] / 2;

    float* out = (float*)d_out;
    float* x2  = out;
    float* ge  = out + (long)n * 64;

    float *h, *x1, *s, *d, *s2, *d2, *gacc, *ws, *ws2;
    int *deg, *rowptr, *wptr, *csrc, *part;
    cudaGetSymbolAddress((void**)&h,      g_h);
    cudaGetSymbolAddress((void**)&x1,     g_x1);
    cudaGetSymbolAddress((void**)&s,      g_s);
    cudaGetSymbolAddress((void**)&d,      g_d);
    cudaGetSymbolAddress((void**)&s2,     g_s2);
    cudaGetSymbolAddress((void**)&d2,     g_d2);
    cudaGetSymbolAddress((void**)&gacc,   g_gacc);
    cudaGetSymbolAddress((void**)&ws,     g_ws);
    cudaGetSymbolAddress((void**)&ws2,    g_ws2);
    cudaGetSymbolAddress((void**)&deg,    g_deg);
    cudaGetSymbolAddress((void**)&rowptr, g_rowptr);
    cudaGetSymbolAddress((void**)&wptr,   g_wptr);
    cudaGetSymbolAddress((void**)&csrc,   g_csrc);
    cudaGetSymbolAddress((void**)&part,   g_part);

    const int TB = 256;
    int ebk = (E + TB - 1) / TB;
    int nwb = (n + 7) / 8;
    int nsb = (n + SCAN_CHUNK - 1) / SCAN_CHUNK;
    const int LGB = 296;           // 2 blocks/SM, 32 nodes per tile

    // 1-3
    prep_ws<72><<<3, TB>>>(W1, as1, ad1, ws);
    filli<<<(n + TB - 1) / TB, TB>>>(deg, 0, n);
    hist_deg<<<ebk, TB>>>(ei, E, deg);
    // 4 (profiled): layer-1 linear + fused s/d
    lin_h<1, 72, 1, 0><<<LGB, TB>>>(x, tf, Wt, bt, W1, ws, h, s, d, gacc, n);
    // 5-8: finish CSR
    scanA<<<nsb, SCAN_CHUNK>>>(deg, n, part);
    scanB<<<1, 1024>>>(part, nsb, n, rowptr);
    scanC<<<nsb, SCAN_CHUNK>>>(deg, n, part, rowptr, wptr);
    scatter_csr<<<ebk, TB>>>(ei, E, wptr, csrc);
    // 9: fold layer-2 attention weights
    prep_ws<64><<<2, TB>>>(W2, as2, ad2, ws2);
    // 10: layer-1 aggregation + fused layer-2 logits
    gat_agg<1, 0><<<nwb, TB>>>(rowptr, csrc, s, d, h, b1, g1, be1, ws2, s2, d2,
                               gacc, x1, n);
    // 11: layer-2 linear (zeroes gacc for the pool epilogue)
    lin_h<0, 64, 0, 1><<<LGB, TB>>>(x1, tf, Wt, bt, W2, ws2, h, s2, d2, gacc, n);
    // 12: layer-2 aggregation + fused global-mean-pool numerator
    gat_agg<0, 1><<<nwb, TB>>>(rowptr, csrc, s2, d2, h, b2, g2, be2, ws2, s2, d2,
                               gacc, x2, n);
    // 13: MLP head
    final_mlp<<<1, 64>>>(gacc, n, Wp1, bp1, Wp2, bp2, ge);
}

// round 12
// speedup vs baseline: 1.1839x; 1.0623x over previous
#include <cuda_runtime.h>
#include <math.h>

#define NMAX 100000
#define EMAX 1600000
#define NEG_SLOPE 0.2f
#define LN_EPS 1e-5f
#define SCAN_CHUNK 512

// ---------------- scratch (device globals; no allocation) ----------------
__device__ __align__(16) float g_h[NMAX * 64];   // per-layer linear output
__device__ __align__(16) float g_x1[NMAX * 64];  // layer-1 output
__device__ __align__(16) float g_s[NMAX * 4];    // layer-1 src logits
__device__ __align__(16) float g_d[NMAX * 4];    // layer-1 dst logits
__device__ __align__(16) float g_s2[NMAX * 4];   // layer-2 src logits
__device__ __align__(16) float g_d2[NMAX * 4];   // layer-2 dst logits
__device__ __align__(16) float g_ws[8 * 72];     // folded attn weights (layer 1)
__device__ __align__(16) float g_ws2[8 * 64];    // folded attn weights (layer 2)
__device__ int   g_deg[NMAX];
__device__ int   g_rowptr[NMAX + 1];
__device__ int   g_wptr[NMAX];
__device__ int   g_csrc[EMAX];
__device__ int   g_part[1024];
__device__ float g_gacc[64];

__device__ __forceinline__ float lrelu(float v) {
    return v > 0.0f ? v : NEG_SLOPE * v;
}

// ---------------- cp.async helpers ----------------
__device__ __forceinline__ unsigned smem_u32(const void* p) {
    return (unsigned)__cvta_generic_to_shared(p);
}
__device__ __forceinline__ void cp16(void* dst, const void* src) {
    asm volatile("cp.async.cg.shared.global [%0], [%1], 16;"
                 :: "r"(smem_u32(dst)), "l"(src));
}
__device__ __forceinline__ void cp_commit() {
    asm volatile("cp.async.commit_group;" ::: "memory");
}
template <int N>
__device__ __forceinline__ void cp_wait() {
    asm volatile("cp.async.wait_group %0;" :: "n"(N) : "memory");
}

// ---------------- small fills ----------------
__global__ void filli(int* p, int v, int n) {
    int i = blockIdx.x * blockDim.x + threadIdx.x;
    if (i < n) p[i] = v;
}

// ---------------- CSR build (scalar) ----------------
__global__ void hist_deg(const int* __restrict__ ei, int E, int* __restrict__ deg) {
    int e = blockIdx.x * blockDim.x + threadIdx.x;
    if (e < E) atomicAdd(&deg[ei[E + e]], 1);
}

__global__ void scanA(const int* __restrict__ deg, int n, int* __restrict__ part) {
    __shared__ int sm[SCAN_CHUNK];
    int gid = blockIdx.x * SCAN_CHUNK + threadIdx.x;
    sm[threadIdx.x] = (gid < n) ? deg[gid] : 0;
    __syncthreads();
    for (int off = SCAN_CHUNK / 2; off > 0; off >>= 1) {
        if (threadIdx.x < off) sm[threadIdx.x] += sm[threadIdx.x + off];
        __syncthreads();
    }
    if (threadIdx.x == 0) part[blockIdx.x] = sm[0];
}

__global__ void scanB(int* __restrict__ part, int nb, int n, int* __restrict__ rowptr) {
    __shared__ int sm[1024];
    int t = threadIdx.x;
    int v = (t < nb) ? part[t] : 0;
    sm[t] = v;
    __syncthreads();
    for (int off = 1; off < 1024; off <<= 1) {
        int add = (t >= off) ? sm[t - off] : 0;
        __syncthreads();
        sm[t] += add;
        __syncthreads();
    }
    if (t < nb) part[t] = sm[t] - v;
    if (t == 1023) rowptr[n] = sm[1023];
}

__global__ void scanC(const int* __restrict__ deg, int n, const int* __restrict__ part,
                      int* __restrict__ rowptr, int* __restrict__ wptr) {
    __shared__ int sm[SCAN_CHUNK];
    int t = threadIdx.x;
    int gid = blockIdx.x * SCAN_CHUNK + t;
    int v = (gid < n) ? deg[gid] : 0;
    sm[t] = v;
    __syncthreads();
    for (int off = 1; off < SCAN_CHUNK; off <<= 1) {
        int add = (t >= off) ? sm[t - off] : 0;
        __syncthreads();
        sm[t] += add;
        __syncthreads();
    }
    if (gid < n) {
        int r = part[blockIdx.x] + sm[t] - v;
        rowptr[gid] = r;
        wptr[gid] = r;
    }
}

__global__ void scatter_csr(const int* __restrict__ ei, int E,
                            int* __restrict__ wptr, int* __restrict__ csrc) {
    int e = blockIdx.x * blockDim.x + threadIdx.x;
    if (e >= E) return;
    int d = ei[E + e];
    int pos = atomicAdd(&wptr[d], 1);
    csrc[pos] = ei[e];
}

// ---------------- fold attention vectors into ws ----------------
template <int IN_DIM>
__global__ void prep_ws(const float* __restrict__ W, const float* __restrict__ a_src,
                        const float* __restrict__ a_dst, float* __restrict__ ws) {
    int idx = blockIdx.x * blockDim.x + threadIdx.x;
    if (idx >= 8 * IN_DIM) return;
    int o = idx / IN_DIM, k = idx % IN_DIM;
    const float* a = (o < 4) ? a_src : a_dst;
    int hd = o & 3;
    float acc = 0.0f;
#pragma unroll
    for (int c = 0; c < 16; c++)
        acc = fmaf(W[k * 64 + hd * 16 + c], a[hd * 16 + c], acc);
    ws[idx] = acc;
}

// ---------------- staging helper (32 nodes per tile) ----------------
template <int TEMP, int IN_DIM>
__device__ __forceinline__ void stage_cp(float* sbuf, const float* __restrict__ in,
                                         const float* __restrict__ tf,
                                         const float* __restrict__ Wt,
                                         const float* __restrict__ bt,
                                         int g0, int n, int tid) {
    if (TEMP) {
        for (int i = tid; i < 32 * 14; i += 256) {
            int nl = i / 14, c4 = i - nl * 14;
            int node = g0 + nl;
            if (node < n)
                cp16(&sbuf[nl * 72 + c4 * 4], &in[(long)node * 56 + c4 * 4]);
        }
        for (int i = tid; i < 32 * 4; i += 256) {
            int nl = i >> 2, q = i & 3;
            int node = g0 + nl;
            if (node < n) {
                float tv = tf[node];
                float4 r;
                r.x = fmaxf(fmaf(tv, Wt[q * 4 + 0], bt[q * 4 + 0]), 0.0f);
                r.y = fmaxf(fmaf(tv, Wt[q * 4 + 1], bt[q * 4 + 1]), 0.0f);
                r.z = fmaxf(fmaf(tv, Wt[q * 4 + 2], bt[q * 4 + 2]), 0.0f);
                r.w = fmaxf(fmaf(tv, Wt[q * 4 + 3], bt[q * 4 + 3]), 0.0f);
                *(float4*)&sbuf[nl * 72 + 56 + q * 4] = r;
            }
        }
    } else {
        for (int i = tid; i < 32 * 16; i += 256) {
            int nl = i >> 4, c4 = i & 15;
            int node = g0 + nl;
            if (node < n)
                cp16(&sbuf[nl * 64 + c4 * 4], &in[(long)node * 64 + c4 * 4]);
        }
    }
}

// ---------------- linear layer: 2 cols/thread + k-split pairs ----------------
template <int TEMP, int IN_DIM, int EPI, int ZG>
__global__ void __launch_bounds__(256, 2)
lin_h(const float* __restrict__ in,
      const float* __restrict__ tf, const float* __restrict__ Wt,
      const float* __restrict__ bt,
      const float* __restrict__ W, const float* __restrict__ ws,
      float* __restrict__ h_out,
      float* __restrict__ s_out, float* __restrict__ d_out_,
      float* __restrict__ gacc, int n) {
    const int K2 = IN_DIM / 2;
    __shared__ float sx[2][32 * IN_DIM];
    __shared__ float sws[EPI ? 8 * IN_DIM : 8];
    int tid = threadIdx.x;
    int half = tid & 1;
    int jj = (tid >> 1) & 31;      // columns jj and jj+32
    int group = tid >> 6;          // 0..3

    if (ZG && blockIdx.x == 0 && tid < 64) gacc[tid] = 0.0f;
    if (EPI) {
        for (int i = tid; i < 8 * IN_DIM; i += 256) sws[i] = ws[i];
    }

    float wreg[2][K2];
#pragma unroll
    for (int k = 0; k < K2; k++) {
        wreg[0][k] = W[(half * K2 + k) * 64 + jj];
        wreg[1][k] = W[(half * K2 + k) * 64 + jj + 32];
    }

    int stride = gridDim.x * 32;
    int g0 = blockIdx.x * 32;
    if (g0 >= n) return;

    stage_cp<TEMP, IN_DIM>(sx[0], in, tf, Wt, bt, g0, n, tid);
    cp_commit();
    int buf = 0;

    for (; g0 < n; g0 += stride) {
        int gn = g0 + stride;
        bool have_next = gn < n;
        if (have_next) {
            stage_cp<TEMP, IN_DIM>(sx[buf ^ 1], in, tf, Wt, bt, gn, n, tid);
            cp_commit();
            cp_wait<1>();
        } else {
            cp_wait<0>();
        }
        __syncthreads();

        float acc0[8], acc1[8];
#pragma unroll
        for (int r = 0; r < 8; r++) { acc0[r] = 0.0f; acc1[r] = 0.0f; }
        const float* xbase = &sx[buf][(group * 8) * IN_DIM + half * K2];
#pragma unroll
        for (int k = 0; k < K2; k += 4) {
#pragma unroll
            for (int r = 0; r < 8; r++) {
                float4 xv = *(const float4*)&xbase[r * IN_DIM + k];
                acc0[r] = fmaf(wreg[0][k + 0], xv.x, acc0[r]);
                acc0[r] = fmaf(wreg[0][k + 1], xv.y, acc0[r]);
                acc0[r] = fmaf(wreg[0][k + 2], xv.z, acc0[r]);
                acc0[r] = fmaf(wreg[0][k + 3], xv.w, acc0[r]);
                acc1[r] = fmaf(wreg[1][k + 0], xv.x, acc1[r]);
                acc1[r] = fmaf(wreg[1][k + 1], xv.y, acc1[r]);
                acc1[r] = fmaf(wreg[1][k + 2], xv.z, acc1[r]);
                acc1[r] = fmaf(wreg[1][k + 3], xv.w, acc1[r]);
            }
        }
#pragma unroll
        for (int r = 0; r < 8; r++) {
            acc0[r] += __shfl_down_sync(0xffffffffu, acc0[r], 1);
            acc1[r] += __shfl_down_sync(0xffffffffu, acc1[r], 1);
        }
        if (half == 0) {
#pragma unroll
            for (int r = 0; r < 8; r++) {
                int node = g0 + group * 8 + r;
                if (node < n) {
                    h_out[(long)node * 64 + jj]      = acc0[r];
                    h_out[(long)node * 64 + jj + 32] = acc1[r];
                }
            }
        }

        if (EPI) {
            int nl = tid >> 3, o = tid & 7;
            int node = g0 + nl;
            if (node < n) {
                const float* xr = &sx[buf][nl * IN_DIM];
                const float* wr = &sws[o * IN_DIM];
                float a2 = 0.0f;
#pragma unroll
                for (int k = 0; k < IN_DIM; k += 4) {
                    float4 xv = *(const float4*)&xr[k];
                    float4 wv = *(const float4*)&wr[k];
                    a2 = fmaf(xv.x, wv.x, a2);
                    a2 = fmaf(xv.y, wv.y, a2);
                    a2 = fmaf(xv.z, wv.z, a2);
                    a2 = fmaf(xv.w, wv.w, a2);
                }
                if (o < 4) s_out[node * 4 + o] = a2;
                else       d_out_[node * 4 + o - 4] = a2;
            }
        }
        __syncthreads();
        buf ^= 1;
    }
}

// ---------------- fused GAT aggregation + softmax-norm + LN + ReLU ----------------
template <int EPI_SD, int EPI_POOL>
__global__ void gat_agg(const int* __restrict__ rowptr, const int* __restrict__ csrc,
                        const float* __restrict__ s_, const float* __restrict__ d_,
                        const float* __restrict__ h_,
                        const float* __restrict__ b,
                        const float* __restrict__ gma, const float* __restrict__ bta,
                        const float* __restrict__ ws2,
                        float* __restrict__ s2_out, float* __restrict__ d2_out,
                        float* __restrict__ gacc,
                        float* __restrict__ out, int n) {
    __shared__ float pool[EPI_POOL ? 8 : 1][EPI_POOL ? 64 : 1];
    int lane = threadIdx.x & 31;
    int sub  = lane >> 4;
    int l    = lane & 15;
    int wid  = threadIdx.x >> 5;
    int node = blockIdx.x * (blockDim.x >> 5) + wid;
    bool valid = node < n;

    if (valid) {
        int head = l >> 2;
        float dlog = d_[node * 4 + head];

        float4 acc = make_float4(0.f, 0.f, 0.f, 0.f);
        float z = 0.0f;
        if (sub == 0) {   // self-loop
            float w = __expf(lrelu(s_[node * 4 + head] + dlog));
            z = w;
            float4 hv = *(const float4*)&h_[(long)node * 64 + l * 4];
            acc = make_float4(w * hv.x, w * hv.y, w * hv.z, w * hv.w);
        }

        int beg = rowptr[node], end = rowptr[node + 1];
        int i = beg + sub;
        for (; i + 6 < end; i += 8) {
            int s0 = csrc[i];
            int s1 = csrc[i + 2];
            int s2 = csrc[i + 4];
            int s3 = csrc[i + 6];
            float e0 = s_[s0 * 4 + head];
            float e1 = s_[s1 * 4 + head];
            float e2 = s_[s2 * 4 + head];
            float e3 = s_[s3 * 4 + head];
            float4 h0 = *(const float4*)&h_[(long)s0 * 64 + l * 4];
            float4 h1 = *(const float4*)&h_[(long)s1 * 64 + l * 4];
            float4 h2 = *(const float4*)&h_[(long)s2 * 64 + l * 4];
            float4 h3 = *(const float4*)&h_[(long)s3 * 64 + l * 4];
            float w0 = __expf(lrelu(e0 + dlog));
            float w1 = __expf(lrelu(e1 + dlog));
            float w2 = __expf(lrelu(e2 + dlog));
            float w3 = __expf(lrelu(e3 + dlog));
            z += (w0 + w1) + (w2 + w3);
            acc.x = fmaf(w0, h0.x, acc.x); acc.x = fmaf(w1, h1.x, acc.x);
            acc.x = fmaf(w2, h2.x, acc.x); acc.x = fmaf(w3, h3.x, acc.x);
            acc.y = fmaf(w0, h0.y, acc.y); acc.y = fmaf(w1, h1.y, acc.y);
            acc.y = fmaf(w2, h2.y, acc.y); acc.y = fmaf(w3, h3.y, acc.y);
            acc.z = fmaf(w0, h0.z, acc.z); acc.z = fmaf(w1, h1.z, acc.z);
            acc.z = fmaf(w2, h2.z, acc.z); acc.z = fmaf(w3, h3.z, acc.z);
            acc.w = fmaf(w0, h0.w, acc.w); acc.w = fmaf(w1, h1.w, acc.w);
            acc.w = fmaf(w2, h2.w, acc.w); acc.w = fmaf(w3, h3.w, acc.w);
        }
        for (; i < end; i += 2) {
            int s0 = csrc[i];
            float w0 = __expf(lrelu(s_[s0 * 4 + head] + dlog));
            float4 h0 = *(const float4*)&h_[(long)s0 * 64 + l * 4];
            z += w0;
            acc.x = fmaf(w0, h0.x, acc.x);
            acc.y = fmaf(w0, h0.y, acc.y);
            acc.z = fmaf(w0, h0.z, acc.z);
            acc.w = fmaf(w0, h0.w, acc.w);
        }

        z     += __shfl_xor_sync(0xffffffffu, z, 16);
        acc.x += __shfl_xor_sync(0xffffffffu, acc.x, 16);
        acc.y += __shfl_xor_sync(0xffffffffu, acc.y, 16);
        acc.z += __shfl_xor_sync(0xffffffffu, acc.z, 16);
        acc.w += __shfl_xor_sync(0xffffffffu, acc.w, 16);

        float zinv = 1.0f / (z + 1e-16f);
        float4 v;
        v.x = acc.x * zinv + b[l * 4 + 0];
        v.y = acc.y * zinv + b[l * 4 + 1];
        v.z = acc.z * zinv + b[l * 4 + 2];
        v.w = acc.w * zinv + b[l * 4 + 3];

        float sum = v.x + v.y + v.z + v.w;
        float sq  = v.x * v.x + v.y * v.y + v.z * v.z + v.w * v.w;
#pragma unroll
        for (int off = 8; off; off >>= 1) {
            sum += __shfl_xor_sync(0xffffffffu, sum, off, 16);
            sq  += __shfl_xor_sync(0xffffffffu, sq, off, 16);
        }
        float mean = sum * (1.0f / 64.0f);
        float var  = sq * (1.0f / 64.0f) - mean * mean;
        float inv  = rsqrtf(var + LN_EPS);
        float4 o;
        o.x = (v.x - mean) * inv * gma[l * 4 + 0] + bta[l * 4 + 0];
        o.y = (v.y - mean) * inv * gma[l * 4 + 1] + bta[l * 4 + 1];
        o.z = (v.z - mean) * inv * gma[l * 4 + 2] + bta[l * 4 + 2];
        o.w = (v.w - mean) * inv * gma[l * 4 + 3] + bta[l * 4 + 3];
        o.x = o.x > 0.0f ? o.x : 0.0f;
        o.y = o.y > 0.0f ? o.y : 0.0f;
        o.z = o.z > 0.0f ? o.z : 0.0f;
        o.w = o.w > 0.0f ? o.w : 0.0f;
        if (sub == 0) {
            *(float4*)&out[(long)node * 64 + l * 4] = o;
            if (EPI_POOL)
                *(float4*)&pool[wid][l * 4] = o;
        }

        if (EPI_SD) {
            float p[8];
#pragma unroll
            for (int q = 0; q < 8; q++) {
                float4 wv = *(const float4*)&ws2[q * 64 + l * 4];
                p[q] = fmaf(o.x, wv.x, 0.0f);
                p[q] = fmaf(o.y, wv.y, p[q]);
                p[q] = fmaf(o.z, wv.z, p[q]);
                p[q] = fmaf(o.w, wv.w, p[q]);
            }
#pragma unroll
            for (int q = 0; q < 8; q++) {
#pragma unroll
                for (int off = 8; off; off >>= 1)
                    p[q] += __shfl_xor_sync(0xffffffffu, p[q], off, 16);
            }
            if (sub == 0 && l == 0) {
                *(float4*)&s2_out[node * 4] = make_float4(p[0], p[1], p[2], p[3]);
                *(float4*)&d2_out[node * 4] = make_float4(p[4], p[5], p[6], p[7]);
            }
        }
    } else if (EPI_POOL && sub == 0) {
        *(float4*)&pool[wid][l * 4] = make_float4(0.f, 0.f, 0.f, 0.f);
    }

    if (EPI_POOL) {
        __syncthreads();
        int t = threadIdx.x;
        if (t < 64) {
            float s = 0.0f;
#pragma unroll
            for (int r = 0; r < 8; r++) s += pool[r][t];
            atomicAdd(&gacc[t], s);
        }
    }
}

// ---------------- final MLP on mean-pooled embedding ----------------
__global__ void final_mlp(const float* __restrict__ acc, int n,
                          const float* __restrict__ Wp1, const float* __restrict__ bp1,
                          const float* __restrict__ Wp2, const float* __restrict__ bp2,
                          float* __restrict__ out) {
    __shared__ float gein[64], hid[64];
    int t = threadIdx.x;
    gein[t] = acc[t] / (float)n;
    __syncthreads();
    float a = bp1[t];
#pragma unroll
    for (int k = 0; k < 64; k++) a = fmaf(gein[k], Wp1[k * 64 + t], a);
    hid[t] = a > 0.0f ? a : 0.0f;
    __syncthreads();
    float o = bp2[t];
#pragma unroll
    for (int k = 0; k < 64; k++) o = fmaf(hid[k], Wp2[k * 64 + t], o);
    out[t] = o;
}

// ---------------- host launch ----------------
extern "C" void kernel_launch(void* const* d_in, const int* in_sizes, int n_in,
                              void* d_out, int out_size) {
    const float* x   = (const float*)d_in[0];
    const float* tf  = (const float*)d_in[1];
    const int*   ei  = (const int*)d_in[2];
    const float* Wt  = (const float*)d_in[3];
    const float* bt  = (const float*)d_in[4];
    const float* W1  = (const float*)d_in[5];
    const float* as1 = (const float*)d_in[6];
    const float* ad1 = (const float*)d_in[7];
    const float* b1  = (const float*)d_in[8];
    const float* g1  = (const float*)d_in[9];
    const float* be1 = (const float*)d_in[10];
    const float* W2  = (const float*)d_in[11];
    const float* as2 = (const float*)d_in[12];
    const float* ad2 = (const float*)d_in[13];
    const float* b2  = (const float*)d_in[14];
    const float* g2  = (const float*)d_in[15];
    const float* be2 = (const float*)d_in[16];
    const float* Wp1 = (const float*)d_in[17];
    const float* bp1 = (const float*)d_in[18];
    const float* Wp2 = (const float*)d_in[19];
    const float* bp2 = (const float*)d_in[20];

    int n = in_sizes[0] / 56;
    int E = in_sizes[2] / 2;

    float* out = (float*)d_out;
    float* x2  = out;
    float* ge  = out + (long)n * 64;

    float *h, *x1, *s, *d, *s2, *d2, *gacc, *ws, *ws2;
    int *deg, *rowptr, *wptr, *csrc, *part;
    cudaGetSymbolAddress((void**)&h,      g_h);
    cudaGetSymbolAddress((void**)&x1,     g_x1);
    cudaGetSymbolAddress((void**)&s,      g_s);
    cudaGetSymbolAddress((void**)&d,      g_d);
    cudaGetSymbolAddress((void**)&s2,     g_s2);
    cudaGetSymbolAddress((void**)&d2,     g_d2);
    cudaGetSymbolAddress((void**)&gacc,   g_gacc);
    cudaGetSymbolAddress((void**)&ws,     g_ws);
    cudaGetSymbolAddress((void**)&ws2,    g_ws2);
    cudaGetSymbolAddress((void**)&deg,    g_deg);
    cudaGetSymbolAddress((void**)&rowptr, g_rowptr);
    cudaGetSymbolAddress((void**)&wptr,   g_wptr);
    cudaGetSymbolAddress((void**)&csrc,   g_csrc);
    cudaGetSymbolAddress((void**)&part,   g_part);

    const int TB = 256;
    int ebk = (E + TB - 1) / TB;
    int nwb = (n + 7) / 8;
    int nsb = (n + SCAN_CHUNK - 1) / SCAN_CHUNK;
    const int LGB = 296;           // 2 blocks/SM, 32 nodes per tile

    // ---- fork a side stream for the CSR build (independent of x path) ----
    cudaStream_t cs;
    cudaStreamCreateWithFlags(&cs, cudaStreamNonBlocking);
    cudaEvent_t evFork, evJoin;
    cudaEventCreateWithFlags(&evFork, cudaEventDisableTiming);
    cudaEventCreateWithFlags(&evJoin, cudaEventDisableTiming);

    cudaEventRecord(evFork, 0);            // fork from main (legacy) stream
    cudaStreamWaitEvent(cs, evFork, 0);

    // main: 1 = prep_ws1
    prep_ws<72><<<3, TB>>>(W1, as1, ad1, ws);
    // side: 2-3
    filli<<<(n + TB - 1) / TB, TB, 0, cs>>>(deg, 0, n);
    hist_deg<<<ebk, TB, 0, cs>>>(ei, E, deg);
    // main: 4 (profiled) = layer-1 linear + fused s/d — overlaps CSR build
    lin_h<1, 72, 1, 0><<<LGB, TB>>>(x, tf, Wt, bt, W1, ws, h, s, d, gacc, n);
    // side: 5-8 finish CSR
    scanA<<<nsb, SCAN_CHUNK, 0, cs>>>(deg, n, part);
    scanB<<<1, 1024, 0, cs>>>(part, nsb, n, rowptr);
    scanC<<<nsb, SCAN_CHUNK, 0, cs>>>(deg, n, part, rowptr, wptr);
    scatter_csr<<<ebk, TB, 0, cs>>>(ei, E, wptr, csrc);
    cudaEventRecord(evJoin, cs);
    // main: 9 = fold layer-2 attention weights (overlaps CSR tail)
    prep_ws<64><<<2, TB>>>(W2, as2, ad2, ws2);

    // join: main waits for CSR completion
    cudaStreamWaitEvent(0, evJoin, 0);

    // 10: layer-1 aggregation + fused layer-2 logits
    gat_agg<1, 0><<<nwb, TB>>>(rowptr, csrc, s, d, h, b1, g1, be1, ws2, s2, d2,
                               gacc, x1, n);
    // 11: layer-2 linear (zeroes gacc for the pool epilogue)
    lin_h<0, 64, 0, 1><<<LGB, TB>>>(x1, tf, Wt, bt, W2, ws2, h, s2, d2, gacc, n);
    // 12: layer-2 aggregation + fused global-mean-pool numerator
    gat_agg<0, 1><<<nwb, TB>>>(rowptr, csrc, s2, d2, h, b2, g2, be2, ws2, s2, d2,
                               gacc, x2, n);
    // 13: MLP head
    final_mlp<<<1, 64>>>(gacc, n, Wp1, bp1, Wp2, bp2, ge);

    // cleanup: only when NOT capturing (destroying capture-associated
    // resources mid-capture is unsafe; the one-time leak during the capture
    // call is host-side only, no device memory involved)
    cudaStreamCaptureStatus cst = cudaStreamCaptureStatusNone;
    cudaStreamIsCapturing(0, &cst);
    if (cst == cudaStreamCaptureStatusNone) {
        cudaEventDestroy(evFork);
        cudaEventDestroy(evJoin);
        cudaStreamDestroy(cs);
    }
}